// round 7
// baseline (speedup 1.0000x reference)
#include <cuda_runtime.h>

#define Bz 4
#define C_IN 32
#define NPIX 4096                        // 64*64 pooled pixels
#define NODES_PER_B (NPIX * C_IN)        // 131072
#define NODES_TOTAL (Bz * NODES_PER_B)   // 524288
#define ADJ_PER_B   ((long)NPIX * NPIX)  // 16777216 floats
#define OUT_FLOATS  (NODES_TOTAL + (long)Bz * ADJ_PER_B)
#define EPSV 1e-6f

// patch certainty for pooled pixel p of batch b (x_var is 1MB, L2-resident)
__device__ __forceinline__ float certainty(const float4* __restrict__ xv4, int b, int p)
{
    int R = p >> 6, C = p & 63;
    float s = 0.f;
    #pragma unroll
    for (int i = 0; i < 4; ++i) {
        float4 v = __ldg(&xv4[((b * 256 + (R * 4 + i)) << 6) + C]);
        s += v.x + v.y + v.z + v.w;
    }
    return 1.f - s * (1.f / 16.f);
}

// One thread per (b, t): pooled node values (tiled 32x) + up to 4 sparse edges.
// Runs after the memset node zeroed everything.
__global__ __launch_bounds__(256) void patch_kernel(
    const float* __restrict__ x_feat,
    const float* __restrict__ x_var,
    float* __restrict__ out)
{
    int g   = blockIdx.x * 256 + threadIdx.x;   // 0..16383
    int b   = g >> 12;
    int t   = g & 4095;
    int R   = t >> 6;
    int Cc  = t & 63;

    // ---- nodes: channel-summed 4x4 pool of x_feat ----
    const float4* xf4 = (const float4*)x_feat;
    float s = 0.f;
    for (int c = 0; c < C_IN; ++c) {
        #pragma unroll
        for (int i = 0; i < 4; ++i) {
            float4 v = __ldcs(&xf4[(((b * C_IN + c) * 256 + (R * 4 + i)) << 6) + Cc]);
            s += v.x + v.y + v.z + v.w;
        }
    }
    s *= (1.f / 16.f);

    float* nodes = out + (long)b * NODES_PER_B;
    #pragma unroll
    for (int j = 0; j < 32; ++j)
        nodes[j * NPIX + t] = s;     // coalesced across t

    // ---- sparse adjacency edges for this (b, t) as destination ----
    const float4* xv4 = (const float4*)x_var;
    float xvt = certainty(xv4, b, t);
    float* adjb = out + NODES_TOTAL + (long)b * ADJ_PER_B;

    if (R + 1 < 64) {                         // from = t+64
        float w = certainty(xv4, b, t + 64) - xvt;
        if (w > EPSV) adjb[(long)(t + 64) * NPIX + t] = w;
    }
    if (R - 1 >= 0) {                         // from = t-64
        float w = certainty(xv4, b, t - 64) - xvt;
        if (w > EPSV) adjb[(long)(t - 64) * NPIX + t] = w;
    }
    if (Cc + 1 < 64) {                        // from = t+1
        float w = certainty(xv4, b, t + 1) - xvt;
        if (w > EPSV) adjb[(long)(t + 1) * NPIX + t] = w;
    }
    if (Cc - 1 >= 0) {                        // from = t-1
        float w = certainty(xv4, b, t - 1) - xvt;
        if (w > EPSV) adjb[(long)(t - 1) * NPIX + t] = w;
    }
}

extern "C" void kernel_launch(void* const* d_in, const int* in_sizes, int n_in,
                              void* d_out, int out_size)
{
    const float* x_feat = (const float*)d_in[0];
    const float* x_var  = (const float*)d_in[1];
    float* out = (float*)d_out;

    // Zero the whole output (270MB) via the driver's fill path (capturable).
    cudaMemsetAsync(out, 0, OUT_FLOATS * sizeof(float));

    // Then write the sparse non-zero content (pool + edges), 64 blocks.
    patch_kernel<<<64, 256>>>(x_feat, x_var, out);
}

// round 8
// speedup vs baseline: 1.2040x; 1.2040x over previous
#include <cuda_runtime.h>

#define Bz 4
#define C_IN 32
#define NPIX 4096                        // 64*64 pooled pixels
#define NODES_PER_B (NPIX * C_IN)        // 131072
#define NODES_TOTAL (Bz * NODES_PER_B)   // 524288
#define ADJ_PER_B   ((long)NPIX * NPIX)  // 16777216 floats
#define EPSV 1e-6f

// patch certainty for pooled pixel p of batch b (x_var is 1MB, L2-resident)
__device__ __forceinline__ float certainty(const float4* __restrict__ xv4, int b, int p)
{
    int R = p >> 6, C = p & 63;
    float s = 0.f;
    #pragma unroll
    for (int i = 0; i < 4; ++i) {
        float4 v = __ldg(&xv4[((b * 256 + (R * 4 + i)) << 6) + C]);
        s += v.x + v.y + v.z + v.w;
    }
    return 1.f - s * (1.f / 16.f);
}

// 2048 blocks; block owns 8 consecutive pooled pixels (same R, Cc0..Cc0+7).
// Coalesced pooling of x_feat + tiled nodes write + sparse edge patches.
__global__ __launch_bounds__(256) void patch_all(
    const float* __restrict__ x_feat,
    const float* __restrict__ x_var,
    float* __restrict__ out)
{
    __shared__ float red[C_IN][8];

    int blk = blockIdx.x;                // 0..2047
    int b   = blk >> 9;                  // batch
    int idx = blk & 511;                 // tile within batch
    int R   = idx >> 3;                  // pooled row
    int Cc0 = (idx & 7) << 3;            // first pooled col of the 8

    int tid   = threadIdx.x;
    int c     = tid >> 3;                // channel 0..31
    int ccoff = tid & 7;                 // which of the 8 pixels

    // ---- pooling: each thread sums 4 rows (one float4 each) of one channel ----
    const float4* xf4 = (const float4*)x_feat;
    float s = 0.f;
    #pragma unroll
    for (int i = 0; i < 4; ++i) {
        // consecutive ccoff -> consecutive float4: coalesced 128B per 8 lanes
        float4 v = __ldcs(&xf4[(((b * C_IN + c) * 256 + (R * 4 + i)) << 6) + Cc0 + ccoff]);
        s += v.x + v.y + v.z + v.w;
    }
    red[c][ccoff] = s;
    __syncthreads();

    // ---- deterministic tree reduction over channels ----
    #pragma unroll
    for (int stride = 16; stride >= 1; stride >>= 1) {
        if (c < stride)
            red[c][ccoff] += red[c + stride][ccoff];
        __syncthreads();
    }

    // ---- nodes: 8 pixels x 32 tiled copies = 256 stores, one per thread ----
    {
        int j = tid >> 3;                                 // copy index 0..31
        int t = R * 64 + Cc0 + ccoff;
        float val = red[0][ccoff] * (1.f / 16.f);
        out[(long)b * NODES_PER_B + j * NPIX + t] = val;  // 8 consecutive per group
    }

    // ---- sparse edges: 8 pixels x 4 directions = 32 tasks (threads 0..31) ----
    if (tid < 32) {
        int co  = tid >> 2;
        int sel = tid & 3;
        int t   = R * 64 + Cc0 + co;
        int f; bool valid;
        if      (sel == 0) { f = t - 64; valid = (R > 0);            }
        else if (sel == 1) { f = t + 64; valid = (R < 63);           }
        else if (sel == 2) { f = t - 1;  valid = ((Cc0 + co) > 0);   }
        else               { f = t + 1;  valid = ((Cc0 + co) < 63);  }
        if (valid) {
            const float4* xv4 = (const float4*)x_var;
            float w = certainty(xv4, b, f) - certainty(xv4, b, t);
            if (w > EPSV)
                out[NODES_TOTAL + (long)b * ADJ_PER_B + (long)f * NPIX + t] = w;
        }
    }
}

extern "C" void kernel_launch(void* const* d_in, const int* in_sizes, int n_in,
                              void* d_out, int out_size)
{
    const float* x_feat = (const float*)d_in[0];
    const float* x_var  = (const float*)d_in[1];
    float* out = (float*)d_out;

    // Driver fill path (~6.4 TB/s, beats kernel STG streams): zero adj only.
    cudaMemsetAsync(out + NODES_TOTAL, 0, (long)Bz * ADJ_PER_B * sizeof(float));

    // Nodes + sparse edges; fully parallel and coalesced.
    patch_all<<<2048, 256>>>(x_feat, x_var, out);
}